// round 1
// baseline (speedup 1.0000x reference)
#include <cuda_runtime.h>
#include <math.h>

// Problem constants (fixed by the dataset)
#define B    16
#define P    2048
#define CIN  512
#define BP   (B*P)
#define K3_BLOCKS (BP/8)   // 4096 blocks, 8 rows per block

// -------- device scratch (no allocations allowed) --------
__device__ unsigned char g_mask[BP];   // 3-bit seed mask per (b,j)
__device__ unsigned char g_ycls[BP];   // assigned class per row (0..3)
__device__ float         g_w[BP];      // assigned weight per row
__device__ int           g_imb[4];     // imbalance counts (integer -> deterministic)
__device__ float         g_partials[K3_BLOCKS];

// ============================================================
// K1: per (b,c) seed masks:  seeds = (cnt<=1) ? onehot(argmax) : (score>0.5)
// grid = B blocks, 256 threads. Also zeroes g_imb.
// ============================================================
__global__ void k1_seeds(const float* __restrict__ pre_score)
{
    int b = blockIdx.x;
    int t = threadIdx.x;
    __shared__ float s_max[256];
    __shared__ int   s_idx[256];
    __shared__ int   s_cnt[256];
    __shared__ float r_max[3];
    __shared__ int   r_idx[3];
    __shared__ int   r_cnt[3];

    if (b == 0 && t < 4) g_imb[t] = 0;

    for (int c = 0; c < 3; c++) {
        float mv = -1e30f; int mi = P; int cnt = 0;
        for (int j = t; j < P; j += 256) {
            float v = pre_score[((b*P) + j)*4 + c];
            cnt += (v > 0.5f) ? 1 : 0;
            if (v > mv) { mv = v; mi = j; }   // j ascending per thread -> first max kept
        }
        s_max[t] = mv; s_idx[t] = mi; s_cnt[t] = cnt;
        __syncthreads();
        for (int s = 128; s > 0; s >>= 1) {
            if (t < s) {
                float v2 = s_max[t+s]; int i2 = s_idx[t+s];
                if (v2 > s_max[t] || (v2 == s_max[t] && i2 < s_idx[t])) {
                    s_max[t] = v2; s_idx[t] = i2;
                }
                s_cnt[t] += s_cnt[t+s];
            }
            __syncthreads();
        }
        if (t == 0) { r_max[c] = s_max[0]; r_idx[c] = s_idx[0]; r_cnt[c] = s_cnt[0]; }
        __syncthreads();
    }

    for (int j = t; j < P; j += 256) {
        unsigned m = 0;
        #pragma unroll
        for (int c = 0; c < 3; c++) {
            float v = pre_score[((b*P) + j)*4 + c];
            bool seed = (r_cnt[c] <= 1) ? (j == r_idx[c]) : (v > 0.5f);
            m |= (seed ? 1u : 0u) << c;
        }
        g_mask[b*P + j] = (unsigned char)m;
    }
}

// ============================================================
// K2: per-proposal seeded IoU argmax (3 classes in one pass) + y/w assignment.
// grid = 256 blocks (16 tiles per batch), 128 threads (1 proposal each).
// Division-free inner loop via cross-product compare.
// ============================================================
__global__ void __launch_bounds__(128) k2_assign(
    const float* __restrict__ rois,
    const float* __restrict__ pre_score,
    const float* __restrict__ labels)
{
    __shared__ float4        sbox[P];    // 32 KB
    __shared__ float         sarea[P];   // 8 KB
    __shared__ unsigned char smk[P];     // 2 KB
    __shared__ int           hist[4];

    int blk  = blockIdx.x;
    int b    = blk >> 4;       // 16 tiles per batch
    int tile = blk & 15;
    int t    = threadIdx.x;

    if (t < 4) hist[t] = 0;

    const float4* rb = (const float4*)(rois + (size_t)b*P*4);
    for (int j = t; j < P; j += 128) {
        float4 v = rb[j];
        sbox[j]  = v;
        sarea[j] = (v.z - v.x) * (v.w - v.y);
        smk[j]   = g_mask[b*P + j];
    }
    __syncthreads();

    int i = tile*128 + t;
    float4 bxi = sbox[i];
    float  ai  = sarea[i];

    float bI[3] = {-1.f, -1.f, -1.f};   // best inter (sentinel -1 => iou -1)
    float bD[3] = { 1.f,  1.f,  1.f};   // best denom
    int   bJ[3] = { 0, 0, 0 };

    #pragma unroll 4
    for (int j = 0; j < P; j++) {
        float4   o  = sbox[j];
        float    aj = sarea[j];
        unsigned m  = smk[j];
        float ltx = fmaxf(bxi.x, o.x);
        float lty = fmaxf(bxi.y, o.y);
        float rbx = fminf(bxi.z, o.z);
        float rby = fminf(bxi.w, o.w);
        float wx  = fmaxf(rbx - ltx, 0.f);
        float wy  = fmaxf(rby - lty, 0.f);
        float inter = wx * wy;
        float den   = ai + aj - inter;
        #pragma unroll
        for (int c = 0; c < 3; c++) {
            // iou > best  <=>  inter*bD > bI*den   (all positive; sentinel bI=-1 handled)
            bool upd = ((m >> c) & 1u) && (inter * bD[c] > bI[c] * den);
            if (upd) { bI[c] = inter; bD[c] = den; bJ[c] = j; }
        }
    }

    // finalize assignment (sequential class order matters)
    float Ibest = -1.f, w = 1.f;
    int ycls = 3;
    #pragma unroll
    for (int c = 0; c < 3; c++) {
        float iou = bI[c] / bD[c];                 // one division per class
        float x   = pre_score[((b*P) + bJ[c])*4 + c];
        bool upd = (labels[b*4 + c] > 0.f) && (iou >= 0.5f) && (iou > Ibest);
        if (upd) { Ibest = iou; w = x; ycls = c; }
    }

    int r = b*P + i;
    g_ycls[r] = (unsigned char)ycls;
    g_w[r]    = w;
    atomicAdd(&hist[ycls], 1);
    __syncthreads();
    if (t < 4 && hist[t]) atomicAdd(&g_imb[t], hist[t]);
}

// ============================================================
// K3: GEMM (row x 512 @ 512x4) + softmax -> logit out, + per-row focal loss
// partial sums. grid = 4096 blocks, 256 threads (warp per row).
// ============================================================
__global__ void __launch_bounds__(256) k3_loss(
    const float* __restrict__ inputs,
    const float* __restrict__ labels,
    const float* __restrict__ fcw,
    const float* __restrict__ fcb,
    float* __restrict__ out)
{
    __shared__ float4 wT[512];   // fcw as float4, row-major: wT[c*128+m]
    __shared__ float  sred[8];

    int t = threadIdx.x;
    const float4* fw4 = (const float4*)fcw;
    for (int idx = t; idx < 512; idx += 256) wT[idx] = fw4[idx];
    __syncthreads();

    int warp = t >> 5, lane = t & 31;
    int row  = blockIdx.x*8 + warp;

    const float4* x4 = (const float4*)(inputs + (size_t)row * CIN);
    float a0 = 0.f, a1 = 0.f, a2 = 0.f, a3 = 0.f;
    #pragma unroll
    for (int u = 0; u < 4; u++) {
        int m = lane + 32*u;
        float4 x  = x4[m];
        float4 w0 = wT[0*128 + m];
        float4 w1 = wT[1*128 + m];
        float4 w2 = wT[2*128 + m];
        float4 w3 = wT[3*128 + m];
        a0 += x.x*w0.x + x.y*w0.y + x.z*w0.z + x.w*w0.w;
        a1 += x.x*w1.x + x.y*w1.y + x.z*w1.z + x.w*w1.w;
        a2 += x.x*w2.x + x.y*w2.y + x.z*w2.z + x.w*w2.w;
        a3 += x.x*w3.x + x.y*w3.y + x.z*w3.z + x.w*w3.w;
    }
    #pragma unroll
    for (int s = 16; s > 0; s >>= 1) {
        a0 += __shfl_xor_sync(0xffffffffu, a0, s);
        a1 += __shfl_xor_sync(0xffffffffu, a1, s);
        a2 += __shfl_xor_sync(0xffffffffu, a2, s);
        a3 += __shfl_xor_sync(0xffffffffu, a3, s);
    }

    float contrib = 0.f;
    if (lane == 0) {
        float xr0 = a0 + fcb[0];
        float xr1 = a1 + fcb[1];
        float xr2 = a2 + fcb[2];
        float xr3 = a3 + fcb[3];
        float mx = fmaxf(fmaxf(xr0, xr1), fmaxf(xr2, xr3));
        float e0 = expf(xr0 - mx), e1 = expf(xr1 - mx);
        float e2 = expf(xr2 - mx), e3 = expf(xr3 - mx);
        float inv = 1.f / (e0 + e1 + e2 + e3);
        float l0 = e0*inv, l1 = e1*inv, l2 = e2*inv, l3 = e3*inv;
        ((float4*)out)[row] = make_float4(l0, l1, l2, l3);

        int   b  = row >> 11;            // /P
        int   k  = (int)g_ycls[row];
        float lk = (k == 0) ? l0 : (k == 1) ? l1 : (k == 2) ? l2 : l3;
        float p  = fminf(fmaxf(lk, 1e-7f), 1.f - 1e-7f);
        float om = 1.f - p;
        float fl = -logf(p) * om * om;          // gamma = 2
        float imbk = (float)g_imb[k];
        float labk = (k == 3) ? 1.f : labels[b*4 + k];
        float wbar = 10.f * expf(lk) * (1.f - labk) + labk;
        contrib = g_w[row] * fl / (imbk + 1e-7f) * wbar;
    }
    if (lane == 0) sred[warp] = contrib;
    __syncthreads();
    if (t == 0) {
        float s = 0.f;
        #pragma unroll
        for (int wi = 0; wi < 8; wi++) s += sred[wi];
        g_partials[blockIdx.x] = s;
    }
}

// ============================================================
// K4: deterministic final reduction: loss = sum(partials) / B
// ============================================================
__global__ void k4_final(float* __restrict__ out)
{
    __shared__ float s[256];
    int t = threadIdx.x;
    float a = 0.f;
    for (int i = t; i < K3_BLOCKS; i += 256) a += g_partials[i];
    s[t] = a;
    __syncthreads();
    for (int r = 128; r > 0; r >>= 1) {
        if (t < r) s[t] += s[t + r];
        __syncthreads();
    }
    if (t == 0) out[BP*4] = s[0] / (float)B;
}

// ============================================================
extern "C" void kernel_launch(void* const* d_in, const int* in_sizes, int n_in,
                              void* d_out, int out_size)
{
    const float* inputs    = (const float*)d_in[0];   // (B*P, 512)
    const float* pre_score = (const float*)d_in[1];   // (B, P, 4)
    const float* labels    = (const float*)d_in[2];   // (B, 4)
    const float* rois      = (const float*)d_in[3];   // (B, P, 4)
    const float* fcw       = (const float*)d_in[4];   // (4, 512)
    const float* fcb       = (const float*)d_in[5];   // (4,)
    float* out = (float*)d_out;                       // logit (B*P*4) ++ loss (1)

    k1_seeds<<<B, 256>>>(pre_score);
    k2_assign<<<256, 128>>>(rois, pre_score, labels);
    k3_loss<<<K3_BLOCKS, 256>>>(inputs, labels, fcw, fcb, out);
    k4_final<<<1, 256>>>(out);
}

// round 2
// speedup vs baseline: 1.2555x; 1.2555x over previous
#include <cuda_runtime.h>
#include <math.h>

#define B    16
#define P    2048
#define CIN  512
#define BP   (B*P)
#define JQ   4
#define JQL  (P/JQ)            // 512 j per quarter
#define TILES_I 16             // 128 i per tile
#define K2_BLOCKS (B*TILES_I*JQ)   // 1024
#define K3_BLOCKS (BP/8)       // 4096

// -------- device scratch (no allocations allowed) --------
__device__ int    g_cnt[B][3];
__device__ int    g_idx[B][3];
__device__ float2 g_pr[JQ][B][P][3];   // per-quarter partial (r, x): 3 MB
__device__ unsigned char g_ycls[BP];
__device__ float  g_w[BP];
__device__ int    g_imb[4];
__device__ unsigned long long g_loss_acc;
__device__ unsigned int g_tick;

// ============================================================
// K1: per (b,c): count(score>0.5) and first-argmax.  grid = 48 blocks.
// Also resets global accumulators (every replay).
// ============================================================
__global__ void k1_seeds(const float* __restrict__ pre_score)
{
    int blk = blockIdx.x;
    int b = blk / 3, c = blk % 3;
    int t = threadIdx.x;
    __shared__ float s_max[256];
    __shared__ int   s_idx[256];
    __shared__ int   s_cnt[256];

    if (blk == 0) {
        if (t < 4) g_imb[t] = 0;
        if (t == 4) g_loss_acc = 0ULL;
        if (t == 5) g_tick = 0u;
    }

    const float4* sb = (const float4*)(pre_score + (size_t)b*P*4);
    float mv = -1e30f; int mi = P; int cnt = 0;
    for (int j = t; j < P; j += 256) {
        float4 v4 = sb[j];
        float v = (c == 0) ? v4.x : (c == 1) ? v4.y : v4.z;
        cnt += (v > 0.5f) ? 1 : 0;
        if (v > mv) { mv = v; mi = j; }     // ascending j per thread
    }
    s_max[t] = mv; s_idx[t] = mi; s_cnt[t] = cnt;
    __syncthreads();
    for (int s = 128; s > 0; s >>= 1) {
        if (t < s) {
            float v2 = s_max[t+s]; int i2 = s_idx[t+s];
            if (v2 > s_max[t] || (v2 == s_max[t] && i2 < s_idx[t])) {
                s_max[t] = v2; s_idx[t] = i2;
            }
            s_cnt[t] += s_cnt[t+s];
        }
        __syncthreads();
    }
    if (t == 0) { g_cnt[b][c] = s_cnt[0]; g_idx[b][c] = s_idx[0]; }
}

// ============================================================
// K2: per (b, i-tile, j-quarter): stable-compacted seeded IoU scan.
// 1024 blocks x 128 threads. One approximate reciprocal per pair;
// per-class update = mul + cmp + 2 sel.
// ============================================================
__global__ void __launch_bounds__(128) k2_partial(
    const float* __restrict__ rois,
    const float* __restrict__ pre_score)
{
    __shared__ float4 cbox[JQL];   // 8 KB
    __shared__ float4 cext[JQL];   // (area, f0, f1, f2) 8 KB
    __shared__ float4 cscr[JQL];   // (s0, s1, s2, s3)   8 KB
    __shared__ int    warp_sum[4];
    __shared__ int    s_n;
    __shared__ int    th_cnt[3], th_idx[3];

    int blk  = blockIdx.x;
    int jq   = blk & 3;
    int tile = (blk >> 2) & 15;
    int b    = blk >> 6;
    int t    = threadIdx.x;
    int lane = t & 31, warp = t >> 5;

    if (t < 3) { th_cnt[t] = g_cnt[b][t]; th_idx[t] = g_idx[b][t]; }
    __syncthreads();

    const float4* rb = (const float4*)(rois      + (size_t)b*P*4);
    const float4* sb = (const float4*)(pre_score + (size_t)b*P*4);

    // ---- stable compaction: thread t owns 4 consecutive j ----
    int jbase = jq*JQL + t*4;
    float4 lbox[4], lscr[4];
    float  lA[4], lf0[4], lf1[4], lf2[4];
    int    keep[4]; int nt = 0;
    #pragma unroll
    for (int u = 0; u < 4; u++) {
        int j = jbase + u;
        float4 bx = rb[j];
        float4 sc = sb[j];
        float f0 = (th_cnt[0] <= 1) ? ((j == th_idx[0]) ? 1.f : 0.f) : ((sc.x > 0.5f) ? 1.f : 0.f);
        float f1 = (th_cnt[1] <= 1) ? ((j == th_idx[1]) ? 1.f : 0.f) : ((sc.y > 0.5f) ? 1.f : 0.f);
        float f2 = (th_cnt[2] <= 1) ? ((j == th_idx[2]) ? 1.f : 0.f) : ((sc.z > 0.5f) ? 1.f : 0.f);
        lbox[u] = bx; lscr[u] = sc;
        lA[u] = (bx.z - bx.x) * (bx.w - bx.y);
        lf0[u] = f0; lf1[u] = f1; lf2[u] = f2;
        keep[u] = (f0 + f1 + f2) > 0.f;
        nt += keep[u];
    }
    int incl = nt;
    #pragma unroll
    for (int s = 1; s < 32; s <<= 1) {
        int v = __shfl_up_sync(0xffffffffu, incl, s);
        if (lane >= s) incl += v;
    }
    if (lane == 31) warp_sum[warp] = incl;
    __syncthreads();
    if (t == 0) {
        int a = 0;
        #pragma unroll
        for (int wq = 0; wq < 4; wq++) { int v = warp_sum[wq]; warp_sum[wq] = a; a += v; }
        s_n = a;
    }
    __syncthreads();
    int pos = warp_sum[warp] + incl - nt;
    #pragma unroll
    for (int u = 0; u < 4; u++) {
        if (keep[u]) {
            cbox[pos] = lbox[u];
            cext[pos] = make_float4(lA[u], lf0[u], lf1[u], lf2[u]);
            cscr[pos] = lscr[u];
            pos++;
        }
    }
    __syncthreads();
    int n = s_n;

    // ---- main scan: one i per thread, all LDS are warp-broadcast ----
    int i = tile*128 + t;
    float4 bxi = rb[i];
    float  ai  = (bxi.z - bxi.x) * (bxi.w - bxi.y);

    float bR0 = -1.f, bR1 = -1.f, bR2 = -1.f;
    int   bK0 = 0,    bK1 = 0,    bK2 = 0;

    #pragma unroll 4
    for (int k = 0; k < n; k++) {
        float4 o = cbox[k];
        float4 e = cext[k];
        float ltx = fmaxf(bxi.x, o.x);
        float lty = fmaxf(bxi.y, o.y);
        float rbx = fminf(bxi.z, o.z);
        float rby = fminf(bxi.w, o.w);
        float wx  = fmaxf(rbx - ltx, 0.f);
        float wy  = fmaxf(rby - lty, 0.f);
        float inter = wx * wy;
        float den   = ai + e.x - inter;
        float rcp;
        asm("rcp.approx.f32 %0, %1;" : "=f"(rcp) : "f"(den));
        float r = inter * rcp;
        float r0 = r * e.y, r1 = r * e.z, r2 = r * e.w;
        if (r0 > bR0) { bR0 = r0; bK0 = k; }
        if (r1 > bR1) { bR1 = r1; bK1 = k; }
        if (r2 > bR2) { bR2 = r2; bK2 = k; }
    }

    float2* pr = &g_pr[jq][b][i][0];
    pr[0] = make_float2(bR0, n ? cscr[bK0].x : 1.f);
    pr[1] = make_float2(bR1, n ? cscr[bK1].y : 1.f);
    pr[2] = make_float2(bR2, n ? cscr[bK2].z : 1.f);
}

// ============================================================
// K_MERGE: merge 4 quarter-partials per (row, class), sequential class
// order, build ycls/w and imbalance histogram. 128 blocks x 256.
// ============================================================
__global__ void k_merge(const float* __restrict__ labels)
{
    __shared__ int hist[4];
    int t = threadIdx.x;
    if (t < 4) hist[t] = 0;
    __syncthreads();

    int r = blockIdx.x*256 + t;
    int b = r >> 11;

    float Ibest = -1.f, w = 1.f; int ycls = 3;
    #pragma unroll
    for (int c = 0; c < 3; c++) {
        float bestr = -1.f, bx = 1.f;
        #pragma unroll
        for (int q = 0; q < 4; q++) {
            float2 p = g_pr[q][b][r & 2047][c];
            if (p.x > bestr) { bestr = p.x; bx = p.y; }   // earliest quarter wins ties
        }
        bool upd = (labels[b*4 + c] > 0.f) && (bestr >= 0.5f) && (bestr > Ibest);
        if (upd) { Ibest = bestr; w = bx; ycls = c; }
    }
    g_ycls[r] = (unsigned char)ycls;
    g_w[r]    = w;
    atomicAdd(&hist[ycls], 1);
    __syncthreads();
    if (t < 4 && hist[t]) atomicAdd(&g_imb[t], hist[t]);
}

// ============================================================
// K3: GEMM (row x 512 @ 512x4) + softmax -> logit, focal loss,
// deterministic fixed-point global reduction, last-block finalize.
// ============================================================
__global__ void __launch_bounds__(256) k3_loss(
    const float* __restrict__ inputs,
    const float* __restrict__ labels,
    const float* __restrict__ fcw,
    const float* __restrict__ fcb,
    float* __restrict__ out)
{
    __shared__ float4 wT[512];
    __shared__ float  sred[8];

    int t = threadIdx.x;
    const float4* fw4 = (const float4*)fcw;
    for (int idx = t; idx < 512; idx += 256) wT[idx] = fw4[idx];
    __syncthreads();

    int warp = t >> 5, lane = t & 31;
    int row  = blockIdx.x*8 + warp;

    const float4* x4 = (const float4*)(inputs + (size_t)row * CIN);
    float a0 = 0.f, a1 = 0.f, a2 = 0.f, a3 = 0.f;
    #pragma unroll
    for (int u = 0; u < 4; u++) {
        int m = lane + 32*u;
        float4 x  = x4[m];
        float4 w0 = wT[0*128 + m];
        float4 w1 = wT[1*128 + m];
        float4 w2 = wT[2*128 + m];
        float4 w3 = wT[3*128 + m];
        a0 += x.x*w0.x + x.y*w0.y + x.z*w0.z + x.w*w0.w;
        a1 += x.x*w1.x + x.y*w1.y + x.z*w1.z + x.w*w1.w;
        a2 += x.x*w2.x + x.y*w2.y + x.z*w2.z + x.w*w2.w;
        a3 += x.x*w3.x + x.y*w3.y + x.z*w3.z + x.w*w3.w;
    }
    #pragma unroll
    for (int s = 16; s > 0; s >>= 1) {
        a0 += __shfl_xor_sync(0xffffffffu, a0, s);
        a1 += __shfl_xor_sync(0xffffffffu, a1, s);
        a2 += __shfl_xor_sync(0xffffffffu, a2, s);
        a3 += __shfl_xor_sync(0xffffffffu, a3, s);
    }

    float contrib = 0.f;
    if (lane == 0) {
        float xr0 = a0 + fcb[0];
        float xr1 = a1 + fcb[1];
        float xr2 = a2 + fcb[2];
        float xr3 = a3 + fcb[3];
        float mx = fmaxf(fmaxf(xr0, xr1), fmaxf(xr2, xr3));
        float e0 = expf(xr0 - mx), e1 = expf(xr1 - mx);
        float e2 = expf(xr2 - mx), e3 = expf(xr3 - mx);
        float inv = 1.f / (e0 + e1 + e2 + e3);
        float l0 = e0*inv, l1 = e1*inv, l2 = e2*inv, l3 = e3*inv;
        ((float4*)out)[row] = make_float4(l0, l1, l2, l3);

        int   b  = row >> 11;
        int   k  = (int)g_ycls[row];
        float lk = (k == 0) ? l0 : (k == 1) ? l1 : (k == 2) ? l2 : l3;
        float p  = fminf(fmaxf(lk, 1e-7f), 1.f - 1e-7f);
        float om = 1.f - p;
        float fl = -logf(p) * om * om;
        float imbk = (float)g_imb[k];
        float labk = (k == 3) ? 1.f : labels[b*4 + k];
        float wbar = 10.f * expf(lk) * (1.f - labk) + labk;
        contrib = g_w[row] * fl / (imbk + 1e-7f) * wbar;
        sred[warp] = contrib;
    }
    __syncthreads();
    if (t == 0) {
        double s = 0.0;
        #pragma unroll
        for (int wi = 0; wi < 8; wi++) s += (double)sred[wi];
        unsigned long long q = (unsigned long long)llrint(s * 4294967296.0);
        atomicAdd(&g_loss_acc, q);
        __threadfence();
        unsigned tick = atomicAdd(&g_tick, 1u);
        if (tick == K3_BLOCKS - 1) {
            unsigned long long acc = atomicAdd(&g_loss_acc, 0ULL);
            out[BP*4] = (float)((double)acc * (1.0/4294967296.0) / (double)B);
        }
    }
}

// ============================================================
extern "C" void kernel_launch(void* const* d_in, const int* in_sizes, int n_in,
                              void* d_out, int out_size)
{
    const float* inputs    = (const float*)d_in[0];
    const float* pre_score = (const float*)d_in[1];
    const float* labels    = (const float*)d_in[2];
    const float* rois      = (const float*)d_in[3];
    const float* fcw       = (const float*)d_in[4];
    const float* fcb       = (const float*)d_in[5];
    float* out = (float*)d_out;

    k1_seeds<<<B*3, 256>>>(pre_score);
    k2_partial<<<K2_BLOCKS, 128>>>(rois, pre_score);
    k_merge<<<BP/256, 256>>>(labels);
    k3_loss<<<K3_BLOCKS, 256>>>(inputs, labels, fcw, fcb, out);
}